// round 8
// baseline (speedup 1.0000x reference)
#include <cuda_runtime.h>
#include <cstddef>

// 3D Haar wavelet (frames valid, h/w 'same' right-zero-pad), all 8 subbands fused.
// x: (2,3,16,256,256) f32. Out: LLL (2,3,15,256,256) then detail (2,3,105,256,256)
// detail order along axis2: LLH, LHL, LHH, HLL, HLH, HHL, HHH
//
// R7 = R5 (h-pairing, scalar boundary loads, __stcs stores) with
// __launch_bounds__(256, 4): cap regs at 64 to fit 4 CTAs/SM (was 72 regs ->
// 3 CTAs, occ 29.7%). More resident warps -> more memory traffic in flight.
// (R6's shuffle boundary regressed; scalar boundary LDGs hit L1 for free.)

#define NBC   6        // 2*3
#define NF    15
#define NH    256
#define NW    256
#define NW4   64       // NW/4
#define NHP   128      // NH/2 output-row pairs
#define FRAME_STRIDE 65536   // 256*256
#define LLL_ELEMS 5898240    // 6*15*65536
#define S3 0.04419417382415922f  // 1/(16*sqrt(2))

__global__ void __launch_bounds__(256, 4) haar3d_kernel(
    const float* __restrict__ x,
    float* __restrict__ out_lll,
    float* __restrict__ out_det)
{
    int idx = blockIdx.x * blockDim.x + threadIdx.x;
    // total threads = NBC*NF*NHP*NW4 = 6*15*128*64 = 737,280 (grid exact)
    int wv   = idx & (NW4 - 1);
    int hp   = (idx >> 6) & (NHP - 1);
    int rest = idx >> 13;          // bc*NF + f
    int f    = rest % NF;
    int bc   = rest / NF;
    int w0   = wv << 2;
    int h0   = hp << 1;            // first output row of the pair (0..254)

    const float* base = x + ((size_t)(bc * 16 + f)) * FRAME_STRIDE + h0 * NW + w0;
    const bool wtail = (wv == NW4 - 1);   // last strip: w0==252
    const bool hend  = (hp == NHP - 1);   // h0==254 -> row h0+2 is zero pad

    // raw rows: frame a = f, frame b = f+1; rows 0..2 = h0, h0+1, h0+2
    float a0[5], a1[5], a2[5], b0[5], b1[5], b2[5];

    #define LOAD_ROW(P, SRC) do {                                   \
        float4 _v = *(const float4*)(SRC);                          \
        P[0]=_v.x; P[1]=_v.y; P[2]=_v.z; P[3]=_v.w;                 \
        P[4] = wtail ? 0.f : (SRC)[4];                              \
    } while (0)

    LOAD_ROW(a0, base);
    LOAD_ROW(a1, base + NW);
    LOAD_ROW(b0, base + FRAME_STRIDE);
    LOAD_ROW(b1, base + FRAME_STRIDE + NW);
    if (!hend) {   // warp-uniform branch
        LOAD_ROW(a2, base + 2 * NW);
        LOAD_ROW(b2, base + FRAME_STRIDE + 2 * NW);
    } else {
        #pragma unroll
        for (int k = 0; k < 5; k++) { a2[k] = 0.f; b2[k] = 0.f; }
    }

    // output bases (row h0); row h0+1 = +NW
    size_t plane = (size_t)h0 * NW + w0;
    float* oL = out_lll + ((size_t)(bc * NF + f)) * FRAME_STRIDE + plane;
    float* oD = out_det + ((size_t)(bc * 7 * NF + f)) * FRAME_STRIDE + plane;

    // Compute + store all 8 subbands for one output row.
    #define DO_ROW(ALO, AHI, BLO, BHI, ROWOFF) do {                              \
        float4 vLLL, vLLH, vLHL, vLHH, vHLL, vHLH, vHHL, vHHH;                   \
        float* rLLL=&vLLL.x; float* rLLH=&vLLH.x; float* rLHL=&vLHL.x;           \
        float* rLHH=&vLHH.x; float* rHLL=&vHLL.x; float* rHLH=&vHLH.x;           \
        float* rHHL=&vHHL.x; float* rHHH=&vHHH.x;                                \
        _Pragma("unroll")                                                        \
        for (int k = 0; k < 4; k++) {                                            \
            float wl00 = ALO[k] + ALO[k+1], wh00 = ALO[k+1] - ALO[k];            \
            float wl01 = AHI[k] + AHI[k+1], wh01 = AHI[k+1] - AHI[k];            \
            float wl10 = BLO[k] + BLO[k+1], wh10 = BLO[k+1] - BLO[k];            \
            float wl11 = BHI[k] + BHI[k+1], wh11 = BHI[k+1] - BHI[k];            \
            float q0LL = wl00 + wl01, q0LH = wh00 + wh01;                        \
            float q0HL = wl01 - wl00, q0HH = wh01 - wh00;                        \
            float q1LL = wl10 + wl11, q1LH = wh10 + wh11;                        \
            float q1HL = wl11 - wl10, q1HH = wh11 - wh10;                        \
            rLLL[k] = S3 * (q0LL + q1LL);                                        \
            rLLH[k] = S3 * (q0LH + q1LH);                                        \
            rLHL[k] = S3 * (q0HL + q1HL);                                        \
            rLHH[k] = S3 * (q0HH + q1HH);                                        \
            rHLL[k] = S3 * (q1LL - q0LL);                                        \
            rHLH[k] = S3 * (q1LH - q0LH);                                        \
            rHHL[k] = S3 * (q1HL - q0HL);                                        \
            rHHH[k] = S3 * (q1HH - q0HH);                                        \
        }                                                                        \
        __stcs((float4*)(oL + (ROWOFF)), vLLL);                                  \
        __stcs((float4*)(oD + (size_t)0 * NF * FRAME_STRIDE + (ROWOFF)), vLLH);  \
        __stcs((float4*)(oD + (size_t)1 * NF * FRAME_STRIDE + (ROWOFF)), vLHL);  \
        __stcs((float4*)(oD + (size_t)2 * NF * FRAME_STRIDE + (ROWOFF)), vLHH);  \
        __stcs((float4*)(oD + (size_t)3 * NF * FRAME_STRIDE + (ROWOFF)), vHLL);  \
        __stcs((float4*)(oD + (size_t)4 * NF * FRAME_STRIDE + (ROWOFF)), vHLH);  \
        __stcs((float4*)(oD + (size_t)5 * NF * FRAME_STRIDE + (ROWOFF)), vHHL);  \
        __stcs((float4*)(oD + (size_t)6 * NF * FRAME_STRIDE + (ROWOFF)), vHHH);  \
    } while (0)

    DO_ROW(a0, a1, b0, b1, 0);     // output row h0   (input rows h0, h0+1)
    DO_ROW(a1, a2, b1, b2, NW);    // output row h0+1 (input rows h0+1, h0+2)

    #undef DO_ROW
    #undef LOAD_ROW
}

extern "C" void kernel_launch(void* const* d_in, const int* in_sizes, int n_in,
                              void* d_out, int out_size)
{
    const float* x = (const float*)d_in[0];
    float* out = (float*)d_out;
    float* out_lll = out;
    float* out_det = out + LLL_ELEMS;

    const int total = NBC * NF * NHP * NW4;  // 737,280
    const int block = 256;
    const int grid = total / block;          // 2880
    haar3d_kernel<<<grid, block>>>(x, out_lll, out_det);
}

// round 9
// speedup vs baseline: 1.3561x; 1.3561x over previous
#include <cuda_runtime.h>
#include <cstddef>

// 3D Haar wavelet (frames valid, h/w 'same' right-zero-pad), all 8 subbands fused.
// x: (2,3,16,256,256) f32. Out: LLL (2,3,15,256,256) then detail (2,3,105,256,256)
// detail order along axis2: LLH, LHL, LHH, HLL, HLH, HHL, HHH
//
// R8 = R5 code (h-pairing, scalar boundary loads, __stcs stores) with
// 128-thread CTAs + __launch_bounds__(128, 7): at 72 regs/thread the RF holds
// 28 warps/SM, but 256-thread CTAs quantize to 24 (3 CTAs). 128-thread CTAs
// fit 7 CTAs = 28 warps (+17%) with the reg budget (65536/896=73 >= 72) intact
// -> no spills (R7's launch_bounds(256,4) squeezed to 64 regs and spilled,
// L1 77%, 45 us).

#define NBC   6        // 2*3
#define NF    15
#define NH    256
#define NW    256
#define NW4   64       // NW/4
#define NHP   128      // NH/2 output-row pairs
#define FRAME_STRIDE 65536   // 256*256
#define LLL_ELEMS 5898240    // 6*15*65536
#define S3 0.04419417382415922f  // 1/(16*sqrt(2))

__global__ void __launch_bounds__(128, 7) haar3d_kernel(
    const float* __restrict__ x,
    float* __restrict__ out_lll,
    float* __restrict__ out_det)
{
    int idx = blockIdx.x * blockDim.x + threadIdx.x;
    // total threads = NBC*NF*NHP*NW4 = 6*15*128*64 = 737,280 (grid exact)
    int wv   = idx & (NW4 - 1);
    int hp   = (idx >> 6) & (NHP - 1);
    int rest = idx >> 13;          // bc*NF + f
    int f    = rest % NF;
    int bc   = rest / NF;
    int w0   = wv << 2;
    int h0   = hp << 1;            // first output row of the pair (0..254)

    const float* base = x + ((size_t)(bc * 16 + f)) * FRAME_STRIDE + h0 * NW + w0;
    const bool wtail = (wv == NW4 - 1);   // last strip: w0==252
    const bool hend  = (hp == NHP - 1);   // h0==254 -> row h0+2 is zero pad

    // raw rows: frame a = f, frame b = f+1; rows 0..2 = h0, h0+1, h0+2
    float a0[5], a1[5], a2[5], b0[5], b1[5], b2[5];

    #define LOAD_ROW(P, SRC) do {                                   \
        float4 _v = *(const float4*)(SRC);                          \
        P[0]=_v.x; P[1]=_v.y; P[2]=_v.z; P[3]=_v.w;                 \
        P[4] = wtail ? 0.f : (SRC)[4];                              \
    } while (0)

    LOAD_ROW(a0, base);
    LOAD_ROW(a1, base + NW);
    LOAD_ROW(b0, base + FRAME_STRIDE);
    LOAD_ROW(b1, base + FRAME_STRIDE + NW);
    if (!hend) {   // warp-uniform branch
        LOAD_ROW(a2, base + 2 * NW);
        LOAD_ROW(b2, base + FRAME_STRIDE + 2 * NW);
    } else {
        #pragma unroll
        for (int k = 0; k < 5; k++) { a2[k] = 0.f; b2[k] = 0.f; }
    }

    // output bases (row h0); row h0+1 = +NW
    size_t plane = (size_t)h0 * NW + w0;
    float* oL = out_lll + ((size_t)(bc * NF + f)) * FRAME_STRIDE + plane;
    float* oD = out_det + ((size_t)(bc * 7 * NF + f)) * FRAME_STRIDE + plane;

    // Compute + store all 8 subbands for one output row.
    #define DO_ROW(ALO, AHI, BLO, BHI, ROWOFF) do {                              \
        float4 vLLL, vLLH, vLHL, vLHH, vHLL, vHLH, vHHL, vHHH;                   \
        float* rLLL=&vLLL.x; float* rLLH=&vLLH.x; float* rLHL=&vLHL.x;           \
        float* rLHH=&vLHH.x; float* rHLL=&vHLL.x; float* rHLH=&vHLH.x;           \
        float* rHHL=&vHHL.x; float* rHHH=&vHHH.x;                                \
        _Pragma("unroll")                                                        \
        for (int k = 0; k < 4; k++) {                                            \
            float wl00 = ALO[k] + ALO[k+1], wh00 = ALO[k+1] - ALO[k];            \
            float wl01 = AHI[k] + AHI[k+1], wh01 = AHI[k+1] - AHI[k];            \
            float wl10 = BLO[k] + BLO[k+1], wh10 = BLO[k+1] - BLO[k];            \
            float wl11 = BHI[k] + BHI[k+1], wh11 = BHI[k+1] - BHI[k];            \
            float q0LL = wl00 + wl01, q0LH = wh00 + wh01;                        \
            float q0HL = wl01 - wl00, q0HH = wh01 - wh00;                        \
            float q1LL = wl10 + wl11, q1LH = wh10 + wh11;                        \
            float q1HL = wl11 - wl10, q1HH = wh11 - wh10;                        \
            rLLL[k] = S3 * (q0LL + q1LL);                                        \
            rLLH[k] = S3 * (q0LH + q1LH);                                        \
            rLHL[k] = S3 * (q0HL + q1HL);                                        \
            rLHH[k] = S3 * (q0HH + q1HH);                                        \
            rHLL[k] = S3 * (q1LL - q0LL);                                        \
            rHLH[k] = S3 * (q1LH - q0LH);                                        \
            rHHL[k] = S3 * (q1HL - q0HL);                                        \
            rHHH[k] = S3 * (q1HH - q0HH);                                        \
        }                                                                        \
        __stcs((float4*)(oL + (ROWOFF)), vLLL);                                  \
        __stcs((float4*)(oD + (size_t)0 * NF * FRAME_STRIDE + (ROWOFF)), vLLH);  \
        __stcs((float4*)(oD + (size_t)1 * NF * FRAME_STRIDE + (ROWOFF)), vLHL);  \
        __stcs((float4*)(oD + (size_t)2 * NF * FRAME_STRIDE + (ROWOFF)), vLHH);  \
        __stcs((float4*)(oD + (size_t)3 * NF * FRAME_STRIDE + (ROWOFF)), vHLL);  \
        __stcs((float4*)(oD + (size_t)4 * NF * FRAME_STRIDE + (ROWOFF)), vHLH);  \
        __stcs((float4*)(oD + (size_t)5 * NF * FRAME_STRIDE + (ROWOFF)), vHHL);  \
        __stcs((float4*)(oD + (size_t)6 * NF * FRAME_STRIDE + (ROWOFF)), vHHH);  \
    } while (0)

    DO_ROW(a0, a1, b0, b1, 0);     // output row h0   (input rows h0, h0+1)
    DO_ROW(a1, a2, b1, b2, NW);    // output row h0+1 (input rows h0+1, h0+2)

    #undef DO_ROW
    #undef LOAD_ROW
}

extern "C" void kernel_launch(void* const* d_in, const int* in_sizes, int n_in,
                              void* d_out, int out_size)
{
    const float* x = (const float*)d_in[0];
    float* out = (float*)d_out;
    float* out_lll = out;
    float* out_det = out + LLL_ELEMS;

    const int total = NBC * NF * NHP * NW4;  // 737,280
    const int block = 128;
    const int grid = total / block;          // 5760
    haar3d_kernel<<<grid, block>>>(x, out_lll, out_det);
}